// round 6
// baseline (speedup 1.0000x reference)
#include <cuda_runtime.h>
#include <cstdint>

#define Pn      96000
#define Mn      32
#define COUTn   64
#define NXn     432
#define NYn     496
#define NBn     8
#define NCELL   (NXn*NYn)          // 214272
#define TOTCELL (NBn*NCELL)        // 1714176
#define NSAMP   (Pn*Mn)            // 3072000

#define KBLOCKS 1184
#define KWARPS  (KBLOCKS*8)        // 9472

// ---------------- scratch (static device globals; no allocations) ----------
__device__ int   g_winner[TOTCELL];                  // 6.9 MB
__device__ float g_part[KBLOCKS][80];                // per-block moment partials
__device__ float g_dmax[Pn*COUTn];                   // unscaled max_m(dot)+E
__device__ float g_dmin[Pn*COUTn];                   // unscaled min_m(dot)+E
__device__ float g_scale[COUTn];
__device__ float g_shift[COUTn];

// ---------------- f32x2 packed helpers (fma/add/mul only; no packed max) ---
typedef unsigned long long u64;
__device__ __forceinline__ u64 pk2(float lo, float hi) {
    u64 r; asm("mov.b64 %0, {%1, %2};" : "=l"(r) : "f"(lo), "f"(hi)); return r;
}
__device__ __forceinline__ void upk2(u64 v, float& lo, float& hi) {
    asm("mov.b64 {%0, %1}, %2;" : "=f"(lo), "=f"(hi) : "l"(v));
}
__device__ __forceinline__ u64 ffma2(u64 a, u64 b, u64 c) {
    u64 d; asm("fma.rn.f32x2 %0, %1, %2, %3;" : "=l"(d) : "l"(a), "l"(b), "l"(c)); return d;
}
__device__ __forceinline__ u64 fmul2(u64 a, u64 b) {
    u64 d; asm("mul.rn.f32x2 %0, %1, %2;" : "=l"(d) : "l"(a), "l"(b)); return d;
}

// ---------------- kernel 0: reset winner array ------------------------------
__global__ void __launch_bounds__(256) kfill_winner() {
    int i = blockIdx.x * 256 + threadIdx.x;
    reinterpret_cast<int4*>(g_winner)[i] = make_int4(-1, -1, -1, -1);
}

// ---------------- kernel W: winner resolution (scatter-set order) -----------
__global__ void __launch_bounds__(256) kwin(const int4* __restrict__ coords) {
    int p = blockIdx.x * 256 + threadIdx.x;
    if (p >= Pn) return;
    int4 c = coords[p];                              // (b, z, y, x)
    int flat = c.x * NCELL + c.y + c.z * NXn + c.w;
    atomicMax(&g_winner[flat], p);                   // highest pillar index wins
}

// ---------------- kernel M: FUSED stats + unscaled dot extremes -------------
// Features f_i = u_i - k_i. One pass over pillars produces:
//   (a) block partials of 14 raw point moments + 66 pillar products (for BN)
//   (b) per (p,c): Dmax/Dmin = extreme_m( x*A_c+y*B_c+z*C_c+w*Dw_c ) + E_u
// BN scale/shift applied later in kscatter (sign of scale picks max vs min).
__global__ void __launch_bounds__(256) kmain(const float4* __restrict__ pil,
                                             const int4*  __restrict__ coords,
                                             const int*   __restrict__ npts,
                                             const float* __restrict__ W) {
    __shared__ __align__(16) float fs[8][4][32];
    __shared__ float sslot[8][66];
    __shared__ float su[8][14];
    __shared__ float sEW[6][64];
    int tid  = threadIdx.x;
    int lane = tid & 31;
    int wInB = tid >> 5;
    int warp = (blockIdx.x * 256 + tid) >> 5;
    int c0 = lane, c1 = lane + 32;

    // stage raw E-weight rows (W[4..9]) into smem
    for (int i = tid; i < 384; i += 256)
        sEW[i >> 6][i & 63] = W[(4 + (i >> 6)) * COUTn + (i & 63)];

    // raw combined weights for the 4-term dot (no BN folding)
    u64 wv0[4], wv1[4];
    {
        float A = W[0*COUTn+c0] + W[4*COUTn+c0] + W[7*COUTn+c0];
        float Bc = W[1*COUTn+c0] + W[5*COUTn+c0] + W[8*COUTn+c0];
        float C = W[2*COUTn+c0] + W[6*COUTn+c0] + W[9*COUTn+c0];
        float Dw = W[3*COUTn+c0];
        wv0[0]=pk2(A,A); wv0[1]=pk2(Bc,Bc); wv0[2]=pk2(C,C); wv0[3]=pk2(Dw,Dw);
        A  = W[0*COUTn+c1] + W[4*COUTn+c1] + W[7*COUTn+c1];
        Bc = W[1*COUTn+c1] + W[5*COUTn+c1] + W[8*COUTn+c1];
        C  = W[2*COUTn+c1] + W[6*COUTn+c1] + W[9*COUTn+c1];
        Dw = W[3*COUTn+c1];
        wv1[0]=pk2(A,A); wv1[1]=pk2(Bc,Bc); wv1[2]=pk2(C,C); wv1[3]=pk2(Dw,Dw);
    }
    __syncthreads();

    // slot mapping for the 66 pillar products q[6] x r[11]
    int i0 = lane / 11,        j0 = lane % 11;
    int i1 = (lane+32) / 11,   j1 = (lane+32) % 11;
    int i2 = (lane+64) / 11,   j2 = (lane+64) % 11;   // junk for lane>=2

    float u1[4]  = {0.f,0.f,0.f,0.f};
    float u2[10] = {0.f,0.f,0.f,0.f,0.f,0.f,0.f,0.f,0.f,0.f};
    float a0 = 0.f, a1 = 0.f, a2 = 0.f;

    int p = warp;
    float4 pt; int4 cd; int np;
    if (p < Pn) { pt = pil[p * Mn + lane]; cd = coords[p]; np = npts[p]; }

    while (p < Pn) {
        int pnx = p + KWARPS;
        float4 ptn; int4 cdn; int npn;
        if (pnx < Pn) { ptn = pil[pnx * Mn + lane]; cdn = coords[pnx]; npn = npts[pnx]; }

        float x = pt.x, y = pt.y, z = pt.z, w = pt.w;
        u1[0] += x; u1[1] += y; u1[2] += z; u1[3] += w;
        u2[0] += x*x; u2[1] += x*y; u2[2] += x*z; u2[3] += x*w;
        u2[4] += y*y; u2[5] += y*z; u2[6] += y*w;
        u2[7] += z*z; u2[8] += z*w; u2[9] += w*w;

        float sx = x, sy = y, sz = z, sw = w;
        #pragma unroll
        for (int off = 16; off; off >>= 1) {
            sx += __shfl_xor_sync(~0u, sx, off);
            sy += __shfl_xor_sync(~0u, sy, off);
            sz += __shfl_xor_sync(~0u, sz, off);
            sw += __shfl_xor_sync(~0u, sw, off);
        }
        float inv = __fdividef(1.0f, (float)np);
        float qa = sx * inv, qb = sy * inv, qc = sz * inv;
        float qd = fmaf((float)cd.w, 0.16f, 0.08f);
        float qe = fmaf((float)cd.z, 0.16f, -39.6f);
        float qg = fmaf((float)cd.y, 4.0f,  -1.0f);

        float qsel = lane==0?qa: lane==1?qb: lane==2?qc: lane==3?qd: lane==4?qe: qg;
        float rsel = lane==0?sx: lane==1?sy: lane==2?sz: lane==3?sw:
                     lane==4?qa: lane==5?qb: lane==6?qc: lane==7?qd:
                     lane==8?qe: lane==9?qg: 32.0f;
        a0 += __shfl_sync(~0u, qsel, i0) * __shfl_sync(~0u, rsel, j0);
        a1 += __shfl_sync(~0u, qsel, i1) * __shfl_sync(~0u, rsel, j1);
        a2 += __shfl_sync(~0u, qsel, i2) * __shfl_sync(~0u, rsel, j2);

        // unscaled E offsets (raw W rows 4..9)
        float E0 = -(qa*sEW[0][c0] + qb*sEW[1][c0] + qc*sEW[2][c0]
                   + qd*sEW[3][c0] + qe*sEW[4][c0] + qg*sEW[5][c0]);
        float E1 = -(qa*sEW[0][c1] + qb*sEW[1][c1] + qc*sEW[2][c1]
                   + qd*sEW[3][c1] + qe*sEW[4][c1] + qg*sEW[5][c1]);

        fs[wInB][0][lane] = x;
        fs[wInB][1][lane] = y;
        fs[wInB][2][lane] = z;
        fs[wInB][3][lane] = w;
        __syncwarp();

        float mx0lo=-3.402823466e38f, mx0hi=-3.402823466e38f;
        float mn0lo= 3.402823466e38f, mn0hi= 3.402823466e38f;
        float mx1lo=-3.402823466e38f, mx1hi=-3.402823466e38f;
        float mn1lo= 3.402823466e38f, mn1hi= 3.402823466e38f;
        #pragma unroll
        for (int mm = 0; mm < 16; mm++) {
            u64 xp = *reinterpret_cast<const u64*>(&fs[wInB][0][2*mm]);
            u64 yp = *reinterpret_cast<const u64*>(&fs[wInB][1][2*mm]);
            u64 zp = *reinterpret_cast<const u64*>(&fs[wInB][2][2*mm]);
            u64 wp = *reinterpret_cast<const u64*>(&fs[wInB][3][2*mm]);
            u64 acc = fmul2(wp, wv0[3]);
            acc = ffma2(zp, wv0[2], acc);
            acc = ffma2(yp, wv0[1], acc);
            acc = ffma2(xp, wv0[0], acc);
            float lo, hi; upk2(acc, lo, hi);
            mx0lo = fmaxf(mx0lo, lo); mx0hi = fmaxf(mx0hi, hi);
            mn0lo = fminf(mn0lo, lo); mn0hi = fminf(mn0hi, hi);
            acc = fmul2(wp, wv1[3]);
            acc = ffma2(zp, wv1[2], acc);
            acc = ffma2(yp, wv1[1], acc);
            acc = ffma2(xp, wv1[0], acc);
            upk2(acc, lo, hi);
            mx1lo = fmaxf(mx1lo, lo); mx1hi = fmaxf(mx1hi, hi);
            mn1lo = fminf(mn1lo, lo); mn1hi = fminf(mn1hi, hi);
        }
        g_dmax[p * COUTn + c0] = fmaxf(mx0lo, mx0hi) + E0;
        g_dmin[p * COUTn + c0] = fminf(mn0lo, mn0hi) + E0;
        g_dmax[p * COUTn + c1] = fmaxf(mx1lo, mx1hi) + E1;
        g_dmin[p * COUTn + c1] = fminf(mn1lo, mn1hi) + E1;
        __syncwarp();

        p = pnx; pt = ptn; cd = cdn; np = npn;
    }

    // block-level reduction of stats partials
    sslot[wInB][lane]      = a0;
    sslot[wInB][lane + 32] = a1;
    if (lane < 2) sslot[wInB][64 + lane] = a2;
    #pragma unroll
    for (int k = 0; k < 14; k++) {
        float v = (k < 4) ? u1[k] : u2[k - 4];
        #pragma unroll
        for (int off = 16; off; off >>= 1) v += __shfl_xor_sync(~0u, v, off);
        if (lane == 0) su[wInB][k] = v;
    }
    __syncthreads();
    if (tid < 66) {
        float s = 0.f;
        #pragma unroll
        for (int w2 = 0; w2 < 8; w2++) s += sslot[w2][tid];
        g_part[blockIdx.x][tid] = s;
    } else if (tid < 80) {
        float s = 0.f;
        #pragma unroll
        for (int w2 = 0; w2 < 8; w2++) s += su[w2][tid - 66];
        g_part[blockIdx.x][tid] = s;
    }
}

// ---------------- kernel B: reconstruct moments, finalize BN ---------------
__global__ void __launch_bounds__(1024) kbn(const float* __restrict__ W,
                                            const float* __restrict__ gamma,
                                            const float* __restrict__ beta) {
    __shared__ float tot[80];
    __shared__ float T2s[10][10];
    __shared__ float T1s[10];
    int tid = threadIdx.x, lane = tid & 31, w = tid >> 5;

    for (int k = w; k < 80; k += 32) {
        float s = 0.f;
        for (int j = lane; j < KBLOCKS; j += 32) s += g_part[j][k];
        #pragma unroll
        for (int off = 16; off; off >>= 1) s += __shfl_xor_sync(~0u, s, off);
        if (lane == 0) tot[k] = s;
    }
    __syncthreads();
    if (tid < 100) {
        int i = tid / 10, j = tid % 10;
        int mi = (i < 4) ? i : (i - 4) % 3;
        int mj = (j < 4) ? j : (j - 4) % 3;
        int aa = min(mi, mj), bb = max(mi, mj);
        float v = tot[70 + 4*aa - (aa*(aa+1))/2 + bb];         // U2
        if (i >= 4) v -= tot[(i - 4) * 11 + mj];
        if (j >= 4) v -= tot[(j - 4) * 11 + mi];
        if (i >= 4 && j >= 4) v += 32.f * tot[(i - 4) * 11 + 4 + (j - 4)];
        T2s[i][j] = v;
    }
    if (tid < 10)
        T1s[tid] = (tid < 4) ? tot[66 + tid]
                             : tot[66 + (tid - 4) % 3] - tot[(tid - 4) * 11 + 10];
    __syncthreads();
    if (tid < COUTn) {
        int c = tid;
        float wc[10];
        #pragma unroll
        for (int i = 0; i < 10; i++) wc[i] = W[i * COUTn + c];
        float mu = 0.f, e2 = 0.f;
        #pragma unroll
        for (int i = 0; i < 10; i++) {
            mu += T1s[i] * wc[i];
            float t = 0.f;
            #pragma unroll
            for (int j = 0; j < 10; j++) t += T2s[i][j] * wc[j];
            e2 += wc[i] * t;
        }
        mu = mu / (float)NSAMP;
        e2 = e2 / (float)NSAMP;
        float var = e2 - mu * mu;
        float sc = gamma[c] * rsqrtf(var + 1e-3f);
        g_scale[c] = sc;
        g_shift[c] = beta[c] - mu * sc;
    }
}

// ---------------- kernel Z: write zero quads (depends only on winner) -------
__global__ void __launch_bounds__(256) kzero(float* __restrict__ out) {
    int q = blockIdx.x * 256 + threadIdx.x;
    if (q >= NCELL / 4) return;
    int b = blockIdx.y;
    int4 w = reinterpret_cast<const int4*>(g_winner)[b * (NCELL / 4) + q];
    if (max(max(w.x, w.y), max(w.z, w.w)) >= 0) return;   // occupied -> kscatter
    float4 z = make_float4(0.f, 0.f, 0.f, 0.f);
    float* base = out + (size_t)b * COUTn * NCELL + (size_t)q * 4;
    #pragma unroll
    for (int cidx = 0; cidx < COUTn; cidx++)
        *reinterpret_cast<float4*>(base + (size_t)cidx * NCELL) = z;
}

// ---------------- kernel S: gather + BN epilogue into occupied quads --------
__device__ __forceinline__ float4 pv4(int wi, int cc, const float* ssc, const float* ssh) {
    if (wi < 0) return make_float4(0.f, 0.f, 0.f, 0.f);
    float4 dx = *reinterpret_cast<const float4*>(&g_dmax[wi * COUTn + cc]);
    float4 dn = *reinterpret_cast<const float4*>(&g_dmin[wi * COUTn + cc]);
    float4 r;
    float s;
    s = ssc[cc+0]; r.x = fmaxf(fmaf(s >= 0.f ? dx.x : dn.x, s, ssh[cc+0]), 0.f);
    s = ssc[cc+1]; r.y = fmaxf(fmaf(s >= 0.f ? dx.y : dn.y, s, ssh[cc+1]), 0.f);
    s = ssc[cc+2]; r.z = fmaxf(fmaf(s >= 0.f ? dx.z : dn.z, s, ssh[cc+2]), 0.f);
    s = ssc[cc+3]; r.w = fmaxf(fmaf(s >= 0.f ? dx.w : dn.w, s, ssh[cc+3]), 0.f);
    return r;
}

__global__ void __launch_bounds__(256) kscatter(float* __restrict__ out) {
    __shared__ float ssc[COUTn], ssh[COUTn];
    int tid = threadIdx.x;
    if (tid < COUTn) { ssc[tid] = g_scale[tid]; ssh[tid] = g_shift[tid]; }
    __syncthreads();
    int q = blockIdx.x * 256 + tid;
    if (q >= NCELL / 4) return;
    int b = blockIdx.y;
    int4 w = reinterpret_cast<const int4*>(g_winner)[b * (NCELL / 4) + q];
    if (max(max(w.x, w.y), max(w.z, w.w)) < 0) return;    // empty -> kzero
    float* base = out + (size_t)b * COUTn * NCELL + (size_t)q * 4;
    #pragma unroll 4
    for (int cc = 0; cc < COUTn; cc += 4) {
        float4 r0 = pv4(w.x, cc, ssc, ssh);
        float4 r1 = pv4(w.y, cc, ssc, ssh);
        float4 r2 = pv4(w.z, cc, ssc, ssh);
        float4 r3 = pv4(w.w, cc, ssc, ssh);
        *reinterpret_cast<float4*>(base + (size_t)(cc + 0) * NCELL) = make_float4(r0.x, r1.x, r2.x, r3.x);
        *reinterpret_cast<float4*>(base + (size_t)(cc + 1) * NCELL) = make_float4(r0.y, r1.y, r2.y, r3.y);
        *reinterpret_cast<float4*>(base + (size_t)(cc + 2) * NCELL) = make_float4(r0.z, r1.z, r2.z, r3.z);
        *reinterpret_cast<float4*>(base + (size_t)(cc + 3) * NCELL) = make_float4(r0.w, r1.w, r2.w, r3.w);
    }
}

// ---------------- launch -----------------------------------------------------
extern "C" void kernel_launch(void* const* d_in, const int* in_sizes, int n_in,
                              void* d_out, int out_size) {
    const float4* pil    = (const float4*)d_in[0];   // (96000, 32, 4) f32
    const int4*   coords = (const int4*)  d_in[1];   // (96000, 4) i32
    const int*    npts   = (const int*)   d_in[2];   // (96000,)   i32
    const float*  W      = (const float*) d_in[3];   // (10, 64)   f32
    const float*  gamma  = (const float*) d_in[4];   // (64,)
    const float*  beta   = (const float*) d_in[5];   // (64,)
    float* out = (float*)d_out;
    (void)in_sizes; (void)n_in; (void)out_size;

    static cudaStream_t s2 = nullptr;
    static cudaEvent_t evA = nullptr, evW = nullptr, evB = nullptr;
    if (!s2) {
        cudaStreamCreateWithFlags(&s2, cudaStreamNonBlocking);
        cudaEventCreateWithFlags(&evA, cudaEventDisableTiming);
        cudaEventCreateWithFlags(&evW, cudaEventDisableTiming);
        cudaEventCreateWithFlags(&evB, cudaEventDisableTiming);
    }

    dim3 qgrid((NCELL / 4 + 255) / 256, NBn);        // (210, 8)

    // side branch: winner init/resolve + zero-fill, overlaps compute chain
    cudaEventRecord(evA, 0);
    cudaStreamWaitEvent(s2, evA, 0);
    kfill_winner<<<TOTCELL / 4 / 256, 256, 0, s2>>>();   // launch 1
    kwin<<<(Pn + 255) / 256, 256, 0, s2>>>(coords);      // launch 2
    cudaEventRecord(evW, s2);                            // winner ready
    kzero<<<qgrid, 256, 0, s2>>>(out);                   // launch 3
    cudaEventRecord(evB, s2);

    // compute chain
    kmain<<<KBLOCKS, 256>>>(pil, coords, npts, W);       // launch 4  <- profiler lands here
    kbn<<<1, 1024>>>(W, gamma, beta);                    // launch 5
    cudaStreamWaitEvent(0, evW, 0);
    kscatter<<<qgrid, 256>>>(out);                       // launch 6 (disjoint quads vs kzero)

    cudaStreamWaitEvent(0, evB, 0);                      // join before capture end
}

// round 7
// speedup vs baseline: 1.2625x; 1.2625x over previous
#include <cuda_runtime.h>
#include <cstdint>

#define Pn      96000
#define Mn      32
#define COUTn   64
#define NXn     432
#define NYn     496
#define NBn     8
#define NCELL   (NXn*NYn)          // 214272
#define TOTCELL (NBn*NCELL)        // 1714176
#define NSAMP   (Pn*Mn)            // 3072000

#define KBLOCKS 1184
#define KWARPS  (KBLOCKS*8)        // 9472

// ---------------- scratch (static device globals; no allocations) ----------
__device__ int   g_winner[TOTCELL];                  // 6.9 MB
__device__ float g_part[KBLOCKS][80];                // per-block moment partials
__device__ float g_dmax[Pn*COUTn];                   // unscaled max_m(dot)+E
__device__ float g_dmin[Pn*COUTn];                   // unscaled min_m(dot)+E
__device__ float g_scale[COUTn];
__device__ float g_shift[COUTn];

// ---------------- f32x2 packed helpers (fma/add/mul only; no packed max) ---
typedef unsigned long long u64;
__device__ __forceinline__ u64 pk2(float lo, float hi) {
    u64 r; asm("mov.b64 %0, {%1, %2};" : "=l"(r) : "f"(lo), "f"(hi)); return r;
}
__device__ __forceinline__ void upk2(u64 v, float& lo, float& hi) {
    asm("mov.b64 {%0, %1}, %2;" : "=f"(lo), "=f"(hi) : "l"(v));
}
__device__ __forceinline__ u64 ffma2(u64 a, u64 b, u64 c) {
    u64 d; asm("fma.rn.f32x2 %0, %1, %2, %3;" : "=l"(d) : "l"(a), "l"(b), "l"(c)); return d;
}
__device__ __forceinline__ u64 fmul2(u64 a, u64 b) {
    u64 d; asm("mul.rn.f32x2 %0, %1, %2;" : "=l"(d) : "l"(a), "l"(b)); return d;
}

// ---------------- kernel 0: reset winner array ------------------------------
__global__ void __launch_bounds__(256) kfill_winner() {
    int i = blockIdx.x * 256 + threadIdx.x;
    reinterpret_cast<int4*>(g_winner)[i] = make_int4(-1, -1, -1, -1);
}

// ---------------- kernel W: winner resolution (scatter-set order) -----------
__global__ void __launch_bounds__(256) kwin(const int4* __restrict__ coords) {
    int p = blockIdx.x * 256 + threadIdx.x;
    if (p >= Pn) return;
    int4 c = coords[p];                              // (b, z, y, x)
    int flat = c.x * NCELL + c.y + c.z * NXn + c.w;
    atomicMax(&g_winner[flat], p);                   // highest pillar index wins
}

// ---------------- kernel M: FUSED stats + unscaled dot extremes -------------
// Features f_i = u_i - k_i. One pass over pillars produces:
//   (a) block partials of 14 raw point moments + 66 pillar products (for BN)
//   (b) per (p,c): Dmax/Dmin = extreme_m( x*A_c+y*B_c+z*C_c+w*Dw_c ) + E_u
// BN scale/shift applied later in kscatter (sign of scale picks max vs min).
__global__ void __launch_bounds__(256, 3) kmain(const float4* __restrict__ pil,
                                                const int4*  __restrict__ coords,
                                                const int*   __restrict__ npts,
                                                const float* __restrict__ W) {
    __shared__ __align__(16) float fs[8][4][32];
    __shared__ float sslot[8][66];
    __shared__ float su[8][14];
    __shared__ float sEW[6][64];
    int tid  = threadIdx.x;
    int lane = tid & 31;
    int wInB = tid >> 5;
    int warp = (blockIdx.x * 256 + tid) >> 5;
    int c0 = lane, c1 = lane + 32;

    // stage raw E-weight rows (W[4..9]) into smem
    for (int i = tid; i < 384; i += 256)
        sEW[i >> 6][i & 63] = W[(4 + (i >> 6)) * COUTn + (i & 63)];

    // raw combined weights for the 4-term dot (no BN folding)
    u64 wv0[4], wv1[4];
    {
        float A  = W[0*COUTn+c0] + W[4*COUTn+c0] + W[7*COUTn+c0];
        float Bc = W[1*COUTn+c0] + W[5*COUTn+c0] + W[8*COUTn+c0];
        float C  = W[2*COUTn+c0] + W[6*COUTn+c0] + W[9*COUTn+c0];
        float Dw = W[3*COUTn+c0];
        wv0[0]=pk2(A,A); wv0[1]=pk2(Bc,Bc); wv0[2]=pk2(C,C); wv0[3]=pk2(Dw,Dw);
        A  = W[0*COUTn+c1] + W[4*COUTn+c1] + W[7*COUTn+c1];
        Bc = W[1*COUTn+c1] + W[5*COUTn+c1] + W[8*COUTn+c1];
        C  = W[2*COUTn+c1] + W[6*COUTn+c1] + W[9*COUTn+c1];
        Dw = W[3*COUTn+c1];
        wv1[0]=pk2(A,A); wv1[1]=pk2(Bc,Bc); wv1[2]=pk2(C,C); wv1[3]=pk2(Dw,Dw);
    }
    __syncthreads();

    // slot mapping for the 66 pillar products q[6] x r[11]
    int i0 = lane / 11,        j0 = lane % 11;
    int i1 = (lane+32) / 11,   j1 = (lane+32) % 11;
    int i2 = (lane+64) / 11,   j2 = (lane+64) % 11;   // junk for lane>=2

    float u1[4]  = {0.f,0.f,0.f,0.f};
    float u2[10] = {0.f,0.f,0.f,0.f,0.f,0.f,0.f,0.f,0.f,0.f};
    float a0 = 0.f, a1 = 0.f, a2 = 0.f;

    for (int p = warp; p < Pn; p += KWARPS) {
        float4 pt = pil[p * Mn + lane];
        int4  cd = coords[p];
        int   np = npts[p];

        float x = pt.x, y = pt.y, z = pt.z, w = pt.w;
        u1[0] += x; u1[1] += y; u1[2] += z; u1[3] += w;
        u2[0] += x*x; u2[1] += x*y; u2[2] += x*z; u2[3] += x*w;
        u2[4] += y*y; u2[5] += y*z; u2[6] += y*w;
        u2[7] += z*z; u2[8] += z*w; u2[9] += w*w;

        float sx = x, sy = y, sz = z, sw = w;
        #pragma unroll
        for (int off = 16; off; off >>= 1) {
            sx += __shfl_xor_sync(~0u, sx, off);
            sy += __shfl_xor_sync(~0u, sy, off);
            sz += __shfl_xor_sync(~0u, sz, off);
            sw += __shfl_xor_sync(~0u, sw, off);
        }
        float inv = __fdividef(1.0f, (float)np);
        float qa = sx * inv, qb = sy * inv, qc = sz * inv;
        float qd = fmaf((float)cd.w, 0.16f, 0.08f);
        float qe = fmaf((float)cd.z, 0.16f, -39.6f);
        float qg = fmaf((float)cd.y, 4.0f,  -1.0f);

        float qsel = lane==0?qa: lane==1?qb: lane==2?qc: lane==3?qd: lane==4?qe: qg;
        float rsel = lane==0?sx: lane==1?sy: lane==2?sz: lane==3?sw:
                     lane==4?qa: lane==5?qb: lane==6?qc: lane==7?qd:
                     lane==8?qe: lane==9?qg: 32.0f;
        a0 += __shfl_sync(~0u, qsel, i0) * __shfl_sync(~0u, rsel, j0);
        a1 += __shfl_sync(~0u, qsel, i1) * __shfl_sync(~0u, rsel, j1);
        a2 += __shfl_sync(~0u, qsel, i2) * __shfl_sync(~0u, rsel, j2);

        fs[wInB][0][lane] = x;
        fs[wInB][1][lane] = y;
        fs[wInB][2][lane] = z;
        fs[wInB][3][lane] = w;
        __syncwarp();

        float mx0lo=-3.402823466e38f, mx0hi=-3.402823466e38f;
        float mn0lo= 3.402823466e38f, mn0hi= 3.402823466e38f;
        float mx1lo=-3.402823466e38f, mx1hi=-3.402823466e38f;
        float mn1lo= 3.402823466e38f, mn1hi= 3.402823466e38f;
        #pragma unroll
        for (int mm = 0; mm < 16; mm++) {
            u64 xp = *reinterpret_cast<const u64*>(&fs[wInB][0][2*mm]);
            u64 yp = *reinterpret_cast<const u64*>(&fs[wInB][1][2*mm]);
            u64 zp = *reinterpret_cast<const u64*>(&fs[wInB][2][2*mm]);
            u64 wp = *reinterpret_cast<const u64*>(&fs[wInB][3][2*mm]);
            u64 acc = fmul2(wp, wv0[3]);
            acc = ffma2(zp, wv0[2], acc);
            acc = ffma2(yp, wv0[1], acc);
            acc = ffma2(xp, wv0[0], acc);
            float lo, hi; upk2(acc, lo, hi);
            mx0lo = fmaxf(mx0lo, lo); mx0hi = fmaxf(mx0hi, hi);
            mn0lo = fminf(mn0lo, lo); mn0hi = fminf(mn0hi, hi);
            acc = fmul2(wp, wv1[3]);
            acc = ffma2(zp, wv1[2], acc);
            acc = ffma2(yp, wv1[1], acc);
            acc = ffma2(xp, wv1[0], acc);
            upk2(acc, lo, hi);
            mx1lo = fmaxf(mx1lo, lo); mx1hi = fmaxf(mx1hi, hi);
            mn1lo = fminf(mn1lo, lo); mn1hi = fminf(mn1hi, hi);
        }
        // unscaled E offsets (raw W rows 4..9), applied post-loop
        float E0 = -(qa*sEW[0][c0] + qb*sEW[1][c0] + qc*sEW[2][c0]
                   + qd*sEW[3][c0] + qe*sEW[4][c0] + qg*sEW[5][c0]);
        float E1 = -(qa*sEW[0][c1] + qb*sEW[1][c1] + qc*sEW[2][c1]
                   + qd*sEW[3][c1] + qe*sEW[4][c1] + qg*sEW[5][c1]);
        g_dmax[p * COUTn + c0] = fmaxf(mx0lo, mx0hi) + E0;
        g_dmin[p * COUTn + c0] = fminf(mn0lo, mn0hi) + E0;
        g_dmax[p * COUTn + c1] = fmaxf(mx1lo, mx1hi) + E1;
        g_dmin[p * COUTn + c1] = fminf(mn1lo, mn1hi) + E1;
        __syncwarp();
    }

    // block-level reduction of stats partials
    sslot[wInB][lane]      = a0;
    sslot[wInB][lane + 32] = a1;
    if (lane < 2) sslot[wInB][64 + lane] = a2;
    #pragma unroll
    for (int k = 0; k < 14; k++) {
        float v = (k < 4) ? u1[k] : u2[k - 4];
        #pragma unroll
        for (int off = 16; off; off >>= 1) v += __shfl_xor_sync(~0u, v, off);
        if (lane == 0) su[wInB][k] = v;
    }
    __syncthreads();
    if (tid < 66) {
        float s = 0.f;
        #pragma unroll
        for (int w2 = 0; w2 < 8; w2++) s += sslot[w2][tid];
        g_part[blockIdx.x][tid] = s;
    } else if (tid < 80) {
        float s = 0.f;
        #pragma unroll
        for (int w2 = 0; w2 < 8; w2++) s += su[w2][tid - 66];
        g_part[blockIdx.x][tid] = s;
    }
}

// ---------------- kernel B: reconstruct moments, finalize BN ---------------
__global__ void __launch_bounds__(1024) kbn(const float* __restrict__ W,
                                            const float* __restrict__ gamma,
                                            const float* __restrict__ beta) {
    __shared__ float tot[80];
    __shared__ float T2s[10][10];
    __shared__ float T1s[10];
    int tid = threadIdx.x, lane = tid & 31, w = tid >> 5;

    for (int k = w; k < 80; k += 32) {
        float s = 0.f;
        for (int j = lane; j < KBLOCKS; j += 32) s += g_part[j][k];
        #pragma unroll
        for (int off = 16; off; off >>= 1) s += __shfl_xor_sync(~0u, s, off);
        if (lane == 0) tot[k] = s;
    }
    __syncthreads();
    if (tid < 100) {
        int i = tid / 10, j = tid % 10;
        int mi = (i < 4) ? i : (i - 4) % 3;
        int mj = (j < 4) ? j : (j - 4) % 3;
        int aa = min(mi, mj), bb = max(mi, mj);
        float v = tot[70 + 4*aa - (aa*(aa+1))/2 + bb];         // U2
        if (i >= 4) v -= tot[(i - 4) * 11 + mj];
        if (j >= 4) v -= tot[(j - 4) * 11 + mi];
        if (i >= 4 && j >= 4) v += 32.f * tot[(i - 4) * 11 + 4 + (j - 4)];
        T2s[i][j] = v;
    }
    if (tid < 10)
        T1s[tid] = (tid < 4) ? tot[66 + tid]
                             : tot[66 + (tid - 4) % 3] - tot[(tid - 4) * 11 + 10];
    __syncthreads();
    if (tid < COUTn) {
        int c = tid;
        float wc[10];
        #pragma unroll
        for (int i = 0; i < 10; i++) wc[i] = W[i * COUTn + c];
        float mu = 0.f, e2 = 0.f;
        #pragma unroll
        for (int i = 0; i < 10; i++) {
            mu += T1s[i] * wc[i];
            float t = 0.f;
            #pragma unroll
            for (int j = 0; j < 10; j++) t += T2s[i][j] * wc[j];
            e2 += wc[i] * t;
        }
        mu = mu / (float)NSAMP;
        e2 = e2 / (float)NSAMP;
        float var = e2 - mu * mu;
        float sc = gamma[c] * rsqrtf(var + 1e-3f);
        g_scale[c] = sc;
        g_shift[c] = beta[c] - mu * sc;
    }
}

// ---------------- kernel Z: DENSE zero of the whole output ------------------
// No predication, no dependencies: hole-free STG.128 stream over all 439 MB.
// kscatter later overwrites the occupied quads (ordered via event).
__global__ void __launch_bounds__(256) kzero(float* __restrict__ out) {
    int q = blockIdx.x * 256 + threadIdx.x;
    if (q >= NCELL / 4) return;
    int b = blockIdx.y;
    float4 z = make_float4(0.f, 0.f, 0.f, 0.f);
    float* base = out + (size_t)b * COUTn * NCELL + (size_t)q * 4;
    #pragma unroll
    for (int cidx = 0; cidx < COUTn; cidx++)
        *reinterpret_cast<float4*>(base + (size_t)cidx * NCELL) = z;
}

// ---------------- kernel S: gather + BN epilogue into occupied quads --------
__device__ __forceinline__ float4 pv4(int wi, int cc, const float* ssc, const float* ssh) {
    if (wi < 0) return make_float4(0.f, 0.f, 0.f, 0.f);
    float4 dx = *reinterpret_cast<const float4*>(&g_dmax[wi * COUTn + cc]);
    float4 dn = *reinterpret_cast<const float4*>(&g_dmin[wi * COUTn + cc]);
    float4 r;
    float s;
    s = ssc[cc+0]; r.x = fmaxf(fmaf(s >= 0.f ? dx.x : dn.x, s, ssh[cc+0]), 0.f);
    s = ssc[cc+1]; r.y = fmaxf(fmaf(s >= 0.f ? dx.y : dn.y, s, ssh[cc+1]), 0.f);
    s = ssc[cc+2]; r.z = fmaxf(fmaf(s >= 0.f ? dx.z : dn.z, s, ssh[cc+2]), 0.f);
    s = ssc[cc+3]; r.w = fmaxf(fmaf(s >= 0.f ? dx.w : dn.w, s, ssh[cc+3]), 0.f);
    return r;
}

__global__ void __launch_bounds__(256) kscatter(float* __restrict__ out) {
    __shared__ float ssc[COUTn], ssh[COUTn];
    int tid = threadIdx.x;
    if (tid < COUTn) { ssc[tid] = g_scale[tid]; ssh[tid] = g_shift[tid]; }
    __syncthreads();
    int q = blockIdx.x * 256 + tid;
    if (q >= NCELL / 4) return;
    int b = blockIdx.y;
    int4 w = reinterpret_cast<const int4*>(g_winner)[b * (NCELL / 4) + q];
    if (max(max(w.x, w.y), max(w.z, w.w)) < 0) return;    // fully empty -> keep zeros
    float* base = out + (size_t)b * COUTn * NCELL + (size_t)q * 4;
    #pragma unroll 4
    for (int cc = 0; cc < COUTn; cc += 4) {
        float4 r0 = pv4(w.x, cc, ssc, ssh);
        float4 r1 = pv4(w.y, cc, ssc, ssh);
        float4 r2 = pv4(w.z, cc, ssc, ssh);
        float4 r3 = pv4(w.w, cc, ssc, ssh);
        *reinterpret_cast<float4*>(base + (size_t)(cc + 0) * NCELL) = make_float4(r0.x, r1.x, r2.x, r3.x);
        *reinterpret_cast<float4*>(base + (size_t)(cc + 1) * NCELL) = make_float4(r0.y, r1.y, r2.y, r3.y);
        *reinterpret_cast<float4*>(base + (size_t)(cc + 2) * NCELL) = make_float4(r0.z, r1.z, r2.z, r3.z);
        *reinterpret_cast<float4*>(base + (size_t)(cc + 3) * NCELL) = make_float4(r0.w, r1.w, r2.w, r3.w);
    }
}

// ---------------- launch -----------------------------------------------------
extern "C" void kernel_launch(void* const* d_in, const int* in_sizes, int n_in,
                              void* d_out, int out_size) {
    const float4* pil    = (const float4*)d_in[0];   // (96000, 32, 4) f32
    const int4*   coords = (const int4*)  d_in[1];   // (96000, 4) i32
    const int*    npts   = (const int*)   d_in[2];   // (96000,)   i32
    const float*  W      = (const float*) d_in[3];   // (10, 64)   f32
    const float*  gamma  = (const float*) d_in[4];   // (64,)
    const float*  beta   = (const float*) d_in[5];   // (64,)
    float* out = (float*)d_out;
    (void)in_sizes; (void)n_in; (void)out_size;

    static cudaStream_t s2 = nullptr;
    static cudaEvent_t evA = nullptr, evB = nullptr;
    if (!s2) {
        cudaStreamCreateWithFlags(&s2, cudaStreamNonBlocking);
        cudaEventCreateWithFlags(&evA, cudaEventDisableTiming);
        cudaEventCreateWithFlags(&evB, cudaEventDisableTiming);
    }

    dim3 qgrid((NCELL / 4 + 255) / 256, NBn);        // (210, 8)

    // fork point for the (dependency-free) dense zero writer
    cudaEventRecord(evA, 0);
    cudaStreamWaitEvent(s2, evA, 0);

    kfill_winner<<<TOTCELL / 4 / 256, 256>>>();      // launch 1 (s0)
    kwin<<<(Pn + 255) / 256, 256>>>(coords);         // launch 2 (s0)
    kmain<<<KBLOCKS, 256>>>(pil, coords, npts, W);   // launch 3 (s0)
    kzero<<<qgrid, 256, 0, s2>>>(out);               // launch 4 (s2) <- profiler lands here
    cudaEventRecord(evB, s2);
    kbn<<<1, 1024>>>(W, gamma, beta);                // launch 5 (s0)
    cudaStreamWaitEvent(0, evB, 0);                  // kzero before kscatter (WAW)
    kscatter<<<qgrid, 256>>>(out);                   // launch 6 (s0)
}